// round 12
// baseline (speedup 1.0000x reference)
#include <cuda_runtime.h>
#include <cuda_bf16.h>

// Single kernel, single launch: 1 CTA per 64x64 image, 256 threads.
// Coefficients per-warp (lanes 0-8 load+clamp, shfl broadcast) - no barrier.
// Thread t: col quad q=t&15 (cols 4q..4q+3), rows 4*(t>>4)..+3.
// Rows read as LDG.128 (L2-resident), halo via warp shuffle; loads front-issued.
// |gx|+|gy| == max(|conv(S)|, |conv(D)|), S=wr+wr^T, D=wr-wr^T.
// Warp min/max via redux.sync.u32 on float bits (g >= 0 -> u32 order == float order),
// cross-warp via 2 smem atomics (lane 0 only) instead of the LDS/FMNMX tree.

#define FULL 0xffffffffu
#define NUM_IMG 2048

__global__ __launch_bounds__(256)
void sobel_norm_kernel(const float* __restrict__ in,
                       const float* __restrict__ w,
                       const float* __restrict__ wf,
                       const float* __restrict__ scale_p,
                       float* __restrict__ out) {
    __shared__ unsigned s_mn, s_mx;

    const int img = blockIdx.x;
    const int tid = threadIdx.x;
    const int lane = tid & 31;
    const int q   = tid & 15;        // col quad 0..15
    const int r0  = (tid >> 4) << 2; // first output row (0..60)
    const int c0  = q << 2;

    // init reduction cells; barrier is at kernel top -> all warps arrive together
    if (tid == 0) { s_mn = 0x7f800000u; s_mx = 0u; }
    __syncthreads();

    const float* __restrict__ base = in + (size_t)img * 4096 + (r0 << 6) + c0;

    auto ldrow4 = [&](int koff, bool valid) -> float4 {
        float4 m = make_float4(0.f, 0.f, 0.f, 0.f);
        if (valid) m = *reinterpret_cast<const float4*>(base + koff);
        return m;
    };

    // ---- Issue ALL 6 row loads up front (MLP=6) ----
    float4 mA = ldrow4(-64, r0 != 0);   // row r0-1
    float4 mB = ldrow4(0,   true);      // row r0
    float4 mC = ldrow4(64,  true);      // row r0+1
    float4 mD = ldrow4(128, true);      // row r0+2
    float4 mE = ldrow4(192, true);      // row r0+3
    float4 mF = ldrow4(256, r0 != 60);  // row r0+4

    // ---- Per-warp coefficient computation (no barrier), hidden under LDGs ----
    float wv = 0.f;
    if (lane < 9) {
        const float f = fminf(fmaxf(__ldg(wf), 1.0f), 255.0f);
        wv = fminf(fmaxf(__ldg(w + lane), -1.0f), 1.0f) * f;
    }
    const float w0 = __shfl_sync(FULL, wv, 0);
    const float w1 = __shfl_sync(FULL, wv, 1);
    const float w2 = __shfl_sync(FULL, wv, 2);
    const float w3 = __shfl_sync(FULL, wv, 3);
    const float w4 = __shfl_sync(FULL, wv, 4);
    const float w5 = __shfl_sync(FULL, wv, 5);
    const float w6 = __shfl_sync(FULL, wv, 6);
    const float w7 = __shfl_sync(FULL, wv, 7);
    const float w8 = __shfl_sync(FULL, wv, 8);

    const float s00 = w0 + w0;
    const float s11 = w4 + w4;
    const float s22 = w8 + w8;
    const float s01 = w1 + w3;
    const float s02 = w2 + w6;
    const float s12 = w5 + w7;
    const float d01 = w1 - w3;
    const float d02 = w2 - w6;
    const float d12 = w5 - w7;

    auto expand = [&](float4 m, float* V) {
        float lf = __shfl_up_sync(FULL, m.w, 1);
        float rg = __shfl_down_sync(FULL, m.x, 1);
        if (q == 0)  lf = 0.f;
        if (q == 15) rg = 0.f;
        V[0] = lf;
        V[1] = m.x; V[2] = m.y; V[3] = m.z; V[4] = m.w;
        V[5] = rg;
    };

    float g[16];
    float gmn = 3.4e38f;
    float gmx = 0.0f;   // g >= 0

    float W[3][6];

    auto conv4 = [&](const float* a, const float* b, const float* c, float* go) {
#pragma unroll
        for (int p = 0; p < 4; p++) {
            const float a0 = a[p], a1 = a[p + 1], a2 = a[p + 2];
            const float b0 = b[p], b1 = b[p + 1], b2 = b[p + 2];
            const float c1 = c[p], c2 = c[p + 1], c3 = c[p + 2];
            float S = s00 * a0;
            S = fmaf(s11, b1, S);
            S = fmaf(s22, c3, S);
            S = fmaf(s01, a1 + b0, S);
            S = fmaf(s02, a2 + c1, S);
            S = fmaf(s12, b2 + c2, S);
            float D = d01 * (a1 - b0);
            D = fmaf(d02, a2 - c1, D);
            D = fmaf(d12, b2 - c2, D);
            const float gv = fmaxf(fabsf(S), fabsf(D));
            go[p] = gv;
            gmn = fminf(gmn, gv);
            gmx = fmaxf(gmx, gv);
        }
    };

    expand(mA, W[0]);
    expand(mB, W[1]);
    expand(mC, W[2]);
    conv4(W[0], W[1], W[2], g + 0);

    expand(mD, W[0]);
    conv4(W[1], W[2], W[0], g + 4);

    expand(mE, W[1]);
    conv4(W[2], W[0], W[1], g + 8);

    expand(mF, W[2]);
    conv4(W[0], W[1], W[2], g + 12);

    // --- warp reduction: integer redux on float bits (all g >= 0) ---
    unsigned wmn_u, wmx_u;
    asm("redux.sync.min.u32 %0, %1, 0xffffffff;" : "=r"(wmn_u) : "r"(__float_as_uint(gmn)));
    asm("redux.sync.max.u32 %0, %1, 0xffffffff;" : "=r"(wmx_u) : "r"(__float_as_uint(gmx)));
    if (lane == 0) {
        atomicMin(&s_mn, wmn_u);
        atomicMax(&s_mx, wmx_u);
    }
    __syncthreads();

    gmn = __uint_as_float(s_mn);   // broadcast LDS
    gmx = __uint_as_float(s_mx);

    const float mul = 255.0f / fmaxf(gmx - gmn, 1.0f);
    const float nb  = -gmn * mul;
    const float sc  = __ldg(scale_p);   // uniform broadcast, L1-warm

    // --- normalize + floor (+scale); float4 stores ---
    float* __restrict__ op = out + (size_t)img * 4096 + (r0 << 6) + c0;
    if (sc == 1.0f) {
#pragma unroll
        for (int i = 0; i < 4; i++) {
            float4 o4;
            o4.x = floorf(fmaf(g[i * 4 + 0], mul, nb));
            o4.y = floorf(fmaf(g[i * 4 + 1], mul, nb));
            o4.z = floorf(fmaf(g[i * 4 + 2], mul, nb));
            o4.w = floorf(fmaf(g[i * 4 + 3], mul, nb));
            *reinterpret_cast<float4*>(op + (i << 6)) = o4;
        }
    } else {
        const float isc = 1.0f / sc;
#pragma unroll
        for (int i = 0; i < 4; i++) {
            float4 o4;
            o4.x = floorf(fmaf(g[i * 4 + 0], mul, nb)) * isc;
            o4.y = floorf(fmaf(g[i * 4 + 1], mul, nb)) * isc;
            o4.z = floorf(fmaf(g[i * 4 + 2], mul, nb)) * isc;
            o4.w = floorf(fmaf(g[i * 4 + 3], mul, nb)) * isc;
            *reinterpret_cast<float4*>(op + (i << 6)) = o4;
        }
    }
}

extern "C" void kernel_launch(void* const* d_in, const int* in_sizes, int n_in,
                              void* d_out, int out_size) {
    const float* in      = (const float*)d_in[0];  // (2048,1,64,64) fp32
    const float* w       = (const float*)d_in[1];  // (1,9) fp32
    const float* wf      = (const float*)d_in[2];  // (1,) fp32
    const float* scale_p = (const float*)d_in[3];  // (1,1) fp32
    float* out = (float*)d_out;                    // (1,2048,1,64,64) fp32
    (void)in_sizes; (void)n_in; (void)out_size;

    sobel_norm_kernel<<<NUM_IMG, 256>>>(in, w, wf, scale_p, out);
}